// round 14
// baseline (speedup 1.0000x reference)
#include <cuda_runtime.h>
#include <cuda_bf16.h>
#include <cstdint>

#define S_LEN 4096
#define BATCH 64
#define ROWS  (S_LEN * BATCH)   // 262144

typedef unsigned long long ull;
typedef uint32_t u32;

// ---------------------------------------------------------------------------
// Scratch (static device globals — no runtime allocation)
// ---------------------------------------------------------------------------
__device__ float g_P  [(size_t)ROWS * 1024];   // P[row][gate 0..1023]  (1.07 GB)
__device__ float g_ys0[(size_t)ROWS * 256];    // layer-0 output [row][hf|hb]
__device__ float g_ys1[(size_t)ROWS * 256];    // layer-1 output
__device__ float g_W  [1024 * 256];            // packed Wih for current layer

// ---------------------------------------------------------------------------
// Helpers
// ---------------------------------------------------------------------------
__device__ __forceinline__ float tanha(float x) {          // HW MUFU.TANH
    float r; asm("tanh.approx.f32 %0, %1;" : "=f"(r) : "f"(x)); return r;
}
__device__ __forceinline__ float sigma(float x) {          // sigmoid via tanh
    return fmaf(tanha(0.5f * x), 0.5f, 0.5f);
}
__device__ __forceinline__ void ffma2(ull& acc, ull a, ull b) {
    asm("fma.rn.f32x2 %0, %1, %2, %0;" : "+l"(acc) : "l"(a), "l"(b));
}
__device__ __forceinline__ float sum2(ull v) {
    float x, y; asm("mov.b64 {%0, %1}, %2;" : "=f"(x), "=f"(y) : "l"(v));
    return x + y;
}
__device__ __forceinline__ u32 bfpk(float lo, float hi) {  // bf16x2 {hi,lo}
    u32 r; asm("cvt.rn.bf16x2.f32 %0, %1, %2;" : "=r"(r) : "f"(hi), "f"(lo));
    return r;
}
__device__ __forceinline__ void mma_bf16(float* c, const u32* a, const u32* b) {
    asm("mma.sync.aligned.m16n8k16.row.col.f32.bf16.bf16.f32 "
        "{%0,%1,%2,%3}, {%4,%5,%6,%7}, {%8,%9}, {%0,%1,%2,%3};"
        : "+f"(c[0]), "+f"(c[1]), "+f"(c[2]), "+f"(c[3])
        : "r"(a[0]), "r"(a[1]), "r"(a[2]), "r"(a[3]), "r"(b[0]), "r"(b[1]));
}

// ---------------------------------------------------------------------------
// pack [wih_f ; wih_b] -> g_W [1024][K]
// ---------------------------------------------------------------------------
__global__ void k_pack(const float* __restrict__ wf, const float* __restrict__ wb,
                       int K) {
    int i = blockIdx.x * blockDim.x + threadIdx.x;
    if (i < 1024 * K) {
        int n = i / K;
        int k = i - n * K;
        g_W[i] = (n < 512) ? wf[n * K + k] : wb[(n - 512) * K + k];
    }
}

// ---------------------------------------------------------------------------
// bf16 tensor-core GEMM:  g_P[row][gate] = sum_k A[row][k] * g_W[gate][k]
// Tile 128(gate) x 128(row) x 32; mma.m16n8k16.bf16; fp32 accumulate.
// (verified in round 13 — unchanged)
// ---------------------------------------------------------------------------
__global__ void __launch_bounds__(256)
k_gemm(const float* __restrict__ x, int useYs0, int K) {
    const float* __restrict__ A = useYs0 ? g_ys0 : x;

    __shared__ __align__(16) u32 Ws[128][20];   // gate tile (bf16x2 along k)
    __shared__ __align__(16) u32 Xs[128][20];   // row tile

    const int tid  = threadIdx.x;
    const int lane = tid & 31;
    const int warp = tid >> 5;
    const int wm   = warp & 1;
    const int wn   = warp >> 1;
    const int lr   = lane >> 2;
    const int lc   = lane & 3;

    const int n0 = blockIdx.x * 128;   // gates
    const int r0 = blockIdx.y * 128;   // rows

    float acc[4][4][4];
#pragma unroll
    for (int mi = 0; mi < 4; mi++)
#pragma unroll
        for (int ni = 0; ni < 4; ni++)
#pragma unroll
            for (int q = 0; q < 4; q++) acc[mi][ni][q] = 0.0f;

    for (int k0 = 0; k0 < K; k0 += 32) {
        __syncthreads();
#pragma unroll
        for (int p = 0; p < 2; p++) {
            int idx = tid + p * 256;
            int r   = idx >> 2;
            int c4  = idx & 3;
            int kf  = c4 * 8;
            float4 wa = *(const float4*)&g_W[(size_t)(n0 + r) * K + k0 + kf];
            float4 wb = *(const float4*)&g_W[(size_t)(n0 + r) * K + k0 + kf + 4];
            float4 aa = *(const float4*)&A [(size_t)(r0 + r) * K + k0 + kf];
            float4 ab = *(const float4*)&A [(size_t)(r0 + r) * K + k0 + kf + 4];
            uint4 wv = make_uint4(bfpk(wa.x, wa.y), bfpk(wa.z, wa.w),
                                  bfpk(wb.x, wb.y), bfpk(wb.z, wb.w));
            uint4 av = make_uint4(bfpk(aa.x, aa.y), bfpk(aa.z, aa.w),
                                  bfpk(ab.x, ab.y), bfpk(ab.z, ab.w));
            *(uint4*)&Ws[r][c4 * 4] = wv;
            *(uint4*)&Xs[r][c4 * 4] = av;
        }
        __syncthreads();

#pragma unroll
        for (int kk = 0; kk < 2; kk++) {
            int k8 = kk * 8;
            u32 afr[4][4], bfr[4][2];
#pragma unroll
            for (int mi = 0; mi < 4; mi++) {
                int mrow = wm * 64 + mi * 16 + lr;
                afr[mi][0] = Xs[mrow    ][k8     + lc];
                afr[mi][1] = Xs[mrow + 8][k8     + lc];
                afr[mi][2] = Xs[mrow    ][k8 + 4 + lc];
                afr[mi][3] = Xs[mrow + 8][k8 + 4 + lc];
            }
#pragma unroll
            for (int ni = 0; ni < 4; ni++) {
                int grow = wn * 32 + ni * 8 + lr;
                bfr[ni][0] = Ws[grow][k8     + lc];
                bfr[ni][1] = Ws[grow][k8 + 4 + lc];
            }
#pragma unroll
            for (int mi = 0; mi < 4; mi++)
#pragma unroll
                for (int ni = 0; ni < 4; ni++)
                    mma_bf16(acc[mi][ni], afr[mi], bfr[ni]);
        }
    }

#pragma unroll
    for (int mi = 0; mi < 4; mi++) {
#pragma unroll
        for (int ni = 0; ni < 4; ni++) {
            size_t rowg = (size_t)r0 + wm * 64 + mi * 16 + lr;
            int    gg   = n0 + wn * 32 + ni * 8 + 2 * lc;
            *(float2*)&g_P[ rowg      * 1024 + gg] =
                make_float2(acc[mi][ni][0], acc[mi][ni][1]);
            *(float2*)&g_P[(rowg + 8) * 1024 + gg] =
                make_float2(acc[mi][ni][2], acc[mi][ni][3]);
        }
    }
}

// ---------------------------------------------------------------------------
// Batch-local recurrent layer: 128 CTAs = (cell, batch), 256 threads.
// Thread pair (u = tid>>1, half = tid&1): all 4 gate rows of unit u over
// K range [half*64, half*64+64).  Rows i,f,g in REGISTERS (192 regs);
// row o in smem (the only per-step weight smem traffic: 1 LDS.128/iter).
// Partials combined via shfl.xor(1); both threads redundantly compute c,h.
// One barrier per step; h double-buffered in smem.
// ---------------------------------------------------------------------------
__global__ void __launch_bounds__(256, 1)
k_recur4(const float* __restrict__ whhf, const float* __restrict__ whhb,
         const float* __restrict__ biasf, const float* __restrict__ biasb,
         int layer) {
    extern __shared__ __align__(16) char smem_raw[];
    ulonglong2* wsm  = (ulonglong2*)smem_raw;                // [16][256] 64 KB
    float*      hbuf = (float*)(smem_raw + 65536);           // [2][128]

    const int tid  = threadIdx.x;
    const int u    = tid >> 1;
    const int half = tid & 1;
    const int b    = blockIdx.x & 63;
    const int cell = blockIdx.x >> 6;

    const float* whh  = cell ? whhb : whhf;
    const float* bias = cell ? biasb : biasf;
    float*       ys   = layer ? g_ys1 : g_ys0;
    const int    hOff = cell * 128;
    const int    kb   = half * 64;

    // ---- weights: rows i,f,g -> regs (k-pair packed); row o -> smem ----
    ull wi[32], wf_[32], wg_[32];
    {
        const ull* ri = (const ull*)(whh + (size_t)(u      ) * 128 + kb);
        const ull* rf = (const ull*)(whh + (size_t)(u + 128) * 128 + kb);
        const ull* rg = (const ull*)(whh + (size_t)(u + 256) * 128 + kb);
        const ulonglong2* ro = (const ulonglong2*)(whh + (size_t)(u + 384) * 128 + kb);
#pragma unroll
        for (int j = 0; j < 32; j++) { wi[j] = ri[j]; wf_[j] = rf[j]; wg_[j] = rg[j]; }
#pragma unroll
        for (int q = 0; q < 16; q++) wsm[q * 256 + tid] = ro[q];
    }

    // ---- bias + P pointer (half0: gates i,f ; half1: gates g,o) ----
    float bA, bB;
    const float* pA;
    if (half == 0) {
        bA = bias[u];       bB = bias[128 + u];
        pA = g_P + (size_t)b * 1024 + cell * 512 + u;
    } else {
        bA = bias[256 + u]; bB = bias[384 + u];
        pA = g_P + (size_t)b * 1024 + cell * 512 + 256 + u;
    }

    if (tid < 128) hbuf[tid] = 0.0f;   // h[-1] = 0 (buffer 0)
    float c_state = 0.0f;
    int   hoff = 0;                    // float-offset of current h buffer
    __syncthreads();

#pragma unroll 1
    for (int t = 0; t < S_LEN; t++) {
        // input projections (independent; LDG hides under matvec)
        float pvA = __ldcg(pA);
        float pvB = __ldcg(pA + 128);
        pA += 65536;                   // next t: +64 rows * 1024

        const float* hb = hbuf + hoff + kb;
        ull aI = 0, aF = 0, aG = 0, aO = 0;
#pragma unroll
        for (int q = 0; q < 16; q++) {
            ulonglong2 h2  = *(const ulonglong2*)&hb[4 * q];   // broadcast LDS
            ulonglong2 wo2 = wsm[q * 256 + tid];                // LDS.128
            ffma2(aI, h2.x, wi [2 * q]);  ffma2(aI, h2.y, wi [2 * q + 1]);
            ffma2(aF, h2.x, wf_[2 * q]);  ffma2(aF, h2.y, wf_[2 * q + 1]);
            ffma2(aG, h2.x, wg_[2 * q]);  ffma2(aG, h2.y, wg_[2 * q + 1]);
            ffma2(aO, h2.x, wo2.x);       ffma2(aO, h2.y, wo2.y);
        }

        float sI = sum2(aI), sF = sum2(aF), sG = sum2(aG), sO = sum2(aO);
        if (half == 0) { sI += pvA + bA; sF += pvB + bB; }
        else           { sG += pvA + bA; sO += pvB + bB; }

        // combine with partner (commutative adds -> bit-identical both sides)
        sI += __shfl_xor_sync(0xffffffffu, sI, 1);
        sF += __shfl_xor_sync(0xffffffffu, sF, 1);
        sG += __shfl_xor_sync(0xffffffffu, sG, 1);
        sO += __shfl_xor_sync(0xffffffffu, sO, 1);

        float si = sigma(sI), sf = sigma(sF);
        float sg = tanha(sG), so = sigma(sO);
        c_state = fmaf(sf, c_state, si * sg);
        float h = so * tanha(c_state);

        if (half == 0) hbuf[(hoff ^ 128) + u] = h;
        else           ys[((size_t)t * 64 + b) * 256 + hOff + u] = h;

        __syncthreads();
        hoff ^= 128;
    }
}

// ---------------------------------------------------------------------------
// out = sigmoid(ys1 @ fc_w^T + fc_b). One warp per row.
// ---------------------------------------------------------------------------
__global__ void __launch_bounds__(256)
k_fc(const float* __restrict__ fc_w, const float* __restrict__ fc_b,
     float* __restrict__ out) {
    int row  = blockIdx.x * 8 + (threadIdx.x >> 5);
    int lane = threadIdx.x & 31;
    const float* y = g_ys1 + (size_t)row * 256;
    float s = 0.0f;
#pragma unroll
    for (int k = lane; k < 256; k += 32) s = fmaf(y[k], fc_w[k], s);
#pragma unroll
    for (int off = 16; off > 0; off >>= 1)
        s += __shfl_xor_sync(0xffffffffu, s, off);
    if (lane == 0) out[row] = sigma(s + fc_b[0]);
}

// ---------------------------------------------------------------------------
// Host entry
// ---------------------------------------------------------------------------
extern "C" void kernel_launch(void* const* d_in, const int* in_sizes, int n_in,
                              void* d_out, int out_size) {
    const float* x     = (const float*)d_in[0];
    const float* wih0f = (const float*)d_in[1];
    const float* whh0f = (const float*)d_in[2];
    const float* b0f   = (const float*)d_in[3];
    const float* wih0b = (const float*)d_in[4];
    const float* whh0b = (const float*)d_in[5];
    const float* b0b   = (const float*)d_in[6];
    const float* wih1f = (const float*)d_in[7];
    const float* whh1f = (const float*)d_in[8];
    const float* b1f   = (const float*)d_in[9];
    const float* wih1b = (const float*)d_in[10];
    const float* whh1b = (const float*)d_in[11];
    const float* b1b   = (const float*)d_in[12];
    const float* fc_w  = (const float*)d_in[13];
    const float* fc_b  = (const float*)d_in[14];
    float* out = (float*)d_out;

    const int smemRec = 65536 + 2 * 128 * 4;   // 66,560 B
    cudaFuncSetAttribute(k_recur4,
                         cudaFuncAttributeMaxDynamicSharedMemorySize, smemRec);

    // layer 0
    k_pack<<<(1024 * 96 + 255) / 256, 256>>>(wih0f, wih0b, 96);
    k_gemm<<<dim3(8, ROWS / 128), 256>>>(x, 0, 96);
    k_recur4<<<128, 256, smemRec>>>(whh0f, whh0b, b0f, b0b, 0);

    // layer 1
    k_pack<<<(1024 * 256 + 255) / 256, 256>>>(wih1f, wih1b, 256);
    k_gemm<<<dim3(8, ROWS / 128), 256>>>(x /*unused*/, 1, 256);
    k_recur4<<<128, 256, smemRec>>>(whh1f, whh1b, b1f, b1b, 1);

    // FC + sigmoid
    k_fc<<<ROWS / 8, 256>>>(fc_w, fc_b, out);
}

// round 15
// speedup vs baseline: 1.4484x; 1.4484x over previous
#include <cuda_runtime.h>
#include <cuda_bf16.h>
#include <cstdint>

#define S_LEN 4096
#define BATCH 64
#define ROWS  (S_LEN * BATCH)   // 262144

typedef unsigned long long ull;
typedef uint32_t u32;

// ---------------------------------------------------------------------------
// Scratch (static device globals — no runtime allocation)
// ---------------------------------------------------------------------------
__device__ float g_P  [(size_t)ROWS * 1024];   // P[row][gate 0..1023]  (1.07 GB)
__device__ float g_ys0[(size_t)ROWS * 256];    // layer-0 output [row][hf|hb]
__device__ float g_ys1[(size_t)ROWS * 256];    // layer-1 output
__device__ float g_W  [1024 * 256];            // packed Wih for current layer

// ---------------------------------------------------------------------------
// Helpers
// ---------------------------------------------------------------------------
__device__ __forceinline__ float tanha(float x) {          // HW MUFU.TANH
    float r; asm("tanh.approx.f32 %0, %1;" : "=f"(r) : "f"(x)); return r;
}
__device__ __forceinline__ float sigma(float x) {          // sigmoid via tanh
    return fmaf(tanha(0.5f * x), 0.5f, 0.5f);
}
__device__ __forceinline__ void ffma2(ull& acc, ull a, ull b) {
    asm("fma.rn.f32x2 %0, %1, %2, %0;" : "+l"(acc) : "l"(a), "l"(b));
}
__device__ __forceinline__ float sum2(ull v) {
    float x, y; asm("mov.b64 {%0, %1}, %2;" : "=f"(x), "=f"(y) : "l"(v));
    return x + y;
}
__device__ __forceinline__ u32 bfpk(float lo, float hi) {  // bf16x2, lo in low
    u32 r; asm("cvt.rn.bf16x2.f32 %0, %1, %2;" : "=r"(r) : "f"(hi), "f"(lo));
    return r;
}
__device__ __forceinline__ ull pku64(u32 lo, u32 hi) {
    ull r; asm("mov.b64 %0, {%1, %2};" : "=l"(r) : "r"(lo), "r"(hi)); return r;
}
// bf16x4 (one ull) -> two f32x2 ulls via PRMT (exact: f32 bits = bf16 << 16)
__device__ __forceinline__ void bf4_unpack(ull p, ull& lo2, ull& hi2) {
    asm("{\n\t"
        ".reg .b32 pl, ph, l0, l1, h0, h1;\n\t"
        "mov.b64 {pl, ph}, %2;\n\t"
        "prmt.b32 l0, pl, 0, 0x1044;\n\t"
        "prmt.b32 l1, pl, 0, 0x3244;\n\t"
        "prmt.b32 h0, ph, 0, 0x1044;\n\t"
        "prmt.b32 h1, ph, 0, 0x3244;\n\t"
        "mov.b64 %0, {l0, l1};\n\t"
        "mov.b64 %1, {h0, h1};\n\t"
        "}" : "=l"(lo2), "=l"(hi2) : "l"(p));
}
__device__ __forceinline__ void mma_bf16(float* c, const u32* a, const u32* b) {
    asm("mma.sync.aligned.m16n8k16.row.col.f32.bf16.bf16.f32 "
        "{%0,%1,%2,%3}, {%4,%5,%6,%7}, {%8,%9}, {%0,%1,%2,%3};"
        : "+f"(c[0]), "+f"(c[1]), "+f"(c[2]), "+f"(c[3])
        : "r"(a[0]), "r"(a[1]), "r"(a[2]), "r"(a[3]), "r"(b[0]), "r"(b[1]));
}

// ---------------------------------------------------------------------------
// pack [wih_f ; wih_b] -> g_W [1024][K]
// ---------------------------------------------------------------------------
__global__ void k_pack(const float* __restrict__ wf, const float* __restrict__ wb,
                       int K) {
    int i = blockIdx.x * blockDim.x + threadIdx.x;
    if (i < 1024 * K) {
        int n = i / K;
        int k = i - n * K;
        g_W[i] = (n < 512) ? wf[n * K + k] : wb[(n - 512) * K + k];
    }
}

// ---------------------------------------------------------------------------
// bf16 tensor-core GEMM with 2-stage smem pipeline:
//   g_P[row][gate] = sum_k A[row][k] * g_W[gate][k]
// ---------------------------------------------------------------------------
__global__ void __launch_bounds__(256)
k_gemm(const float* __restrict__ x, int useYs0, int K) {
    const float* __restrict__ A = useYs0 ? g_ys0 : x;

    __shared__ __align__(16) u32 Ws[2][128][20];
    __shared__ __align__(16) u32 Xs[2][128][20];

    const int tid  = threadIdx.x;
    const int lane = tid & 31;
    const int warp = tid >> 5;
    const int wm   = warp & 1;
    const int wn   = warp >> 1;
    const int lr   = lane >> 2;
    const int lc   = lane & 3;

    const int n0 = blockIdx.x * 128;   // gates
    const int r0 = blockIdx.y * 128;   // rows
    const int NC = K >> 5;             // 32-k chunks

    float acc[4][4][4];
#pragma unroll
    for (int mi = 0; mi < 4; mi++)
#pragma unroll
        for (int ni = 0; ni < 4; ni++)
#pragma unroll
            for (int q = 0; q < 4; q++) acc[mi][ni][q] = 0.0f;

    float4 wv[2][2], av[2][2];

    // ---- per-chunk load (LDG -> regs) ----
    auto ldg_chunk = [&](int c) {
        int k0 = c * 32;
#pragma unroll
        for (int p = 0; p < 2; p++) {
            int idx = tid + p * 256;
            int r   = idx >> 2;
            int kf  = (idx & 3) * 8;
            wv[p][0] = *(const float4*)&g_W[(size_t)(n0 + r) * K + k0 + kf];
            wv[p][1] = *(const float4*)&g_W[(size_t)(n0 + r) * K + k0 + kf + 4];
            av[p][0] = *(const float4*)&A [(size_t)(r0 + r) * K + k0 + kf];
            av[p][1] = *(const float4*)&A [(size_t)(r0 + r) * K + k0 + kf + 4];
        }
    };
    // ---- convert + STS into stage st ----
    auto sts_chunk = [&](int st) {
#pragma unroll
        for (int p = 0; p < 2; p++) {
            int idx = tid + p * 256;
            int r   = idx >> 2;
            int c4  = idx & 3;
            uint4 wq = make_uint4(bfpk(wv[p][0].x, wv[p][0].y), bfpk(wv[p][0].z, wv[p][0].w),
                                  bfpk(wv[p][1].x, wv[p][1].y), bfpk(wv[p][1].z, wv[p][1].w));
            uint4 aq = make_uint4(bfpk(av[p][0].x, av[p][0].y), bfpk(av[p][0].z, av[p][0].w),
                                  bfpk(av[p][1].x, av[p][1].y), bfpk(av[p][1].z, av[p][1].w));
            *(uint4*)&Ws[st][r][c4 * 4] = wq;
            *(uint4*)&Xs[st][r][c4 * 4] = aq;
        }
    };
    // ---- mma on stage st ----
    auto mma_chunk = [&](int st) {
#pragma unroll
        for (int kk = 0; kk < 2; kk++) {
            int k8 = kk * 8;
            u32 afr[4][4], bfr[4][2];
#pragma unroll
            for (int mi = 0; mi < 4; mi++) {
                int mrow = wm * 64 + mi * 16 + lr;
                afr[mi][0] = Xs[st][mrow    ][k8     + lc];
                afr[mi][1] = Xs[st][mrow + 8][k8     + lc];
                afr[mi][2] = Xs[st][mrow    ][k8 + 4 + lc];
                afr[mi][3] = Xs[st][mrow + 8][k8 + 4 + lc];
            }
#pragma unroll
            for (int ni = 0; ni < 4; ni++) {
                int grow = wn * 32 + ni * 8 + lr;
                bfr[ni][0] = Ws[st][grow][k8     + lc];
                bfr[ni][1] = Ws[st][grow][k8 + 4 + lc];
            }
#pragma unroll
            for (int mi = 0; mi < 4; mi++)
#pragma unroll
                for (int ni = 0; ni < 4; ni++)
                    mma_bf16(acc[mi][ni], afr[mi], bfr[ni]);
        }
    };

    // prologue
    ldg_chunk(0);
    sts_chunk(0);
    __syncthreads();
    for (int c = 1; c < NC; c++) {
        ldg_chunk(c);                 // LDG in flight
        mma_chunk((c - 1) & 1);       // compute on previous stage
        sts_chunk(c & 1);             // write idle stage
        __syncthreads();
    }
    mma_chunk((NC - 1) & 1);

#pragma unroll
    for (int mi = 0; mi < 4; mi++) {
#pragma unroll
        for (int ni = 0; ni < 4; ni++) {
            size_t rowg = (size_t)r0 + wm * 64 + mi * 16 + lr;
            int    gg   = n0 + wn * 32 + ni * 8 + 2 * lc;
            *(float2*)&g_P[ rowg      * 1024 + gg] =
                make_float2(acc[mi][ni][0], acc[mi][ni][1]);
            *(float2*)&g_P[(rowg + 8) * 1024 + gg] =
                make_float2(acc[mi][ni][2], acc[mi][ni][3]);
        }
    }
}

// ---------------------------------------------------------------------------
// Batch-local recurrent layer: 128 CTAs = (cell, batch), 256 threads.
// Thread pair (u = tid>>1, half = tid&1): 4 gate rows of unit u over
// K range [half*64 .. +64).  Rows i,f fp32 in regs (proven recur3 load);
// rows g,o in smem as bf16x4 packs -> HALF the crossbar traffic, PRMT unpack.
// Partials combined via shfl.xor(1); one barrier per step; h double-buffered.
// ---------------------------------------------------------------------------
__global__ void __launch_bounds__(256, 1)
k_recur5(const float* __restrict__ whhf, const float* __restrict__ whhb,
         const float* __restrict__ biasf, const float* __restrict__ biasb,
         int layer) {
    extern __shared__ __align__(16) char smem_raw[];
    ulonglong2* wsm = (ulonglong2*)smem_raw;                 // [16][256] 64 KB
    float (*hbuf)[128] = (float(*)[128])(smem_raw + 65536);  // [2][128]

    const int tid  = threadIdx.x;
    const int u    = tid >> 1;
    const int half = tid & 1;
    const int b    = blockIdx.x & 63;
    const int cell = blockIdx.x >> 6;

    const float* whh  = cell ? whhb : whhf;
    const float* bias = cell ? biasb : biasf;
    float*       ys   = layer ? g_ys1 : g_ys0;
    const int    hOff = cell * 128;
    const int    kb   = half * 64;

    // ---- weights: rows i,f -> regs (k-pair packed); rows g,o -> smem bf16 ----
    ull wi[32], wf_[32];
    {
        const ull* ri = (const ull*)(whh + (size_t)(u      ) * 128 + kb);
        const ull* rf = (const ull*)(whh + (size_t)(u + 128) * 128 + kb);
#pragma unroll
        for (int j = 0; j < 32; j++) { wi[j] = ri[j]; wf_[j] = rf[j]; }
        const float* rg = whh + (size_t)(u + 256) * 128 + kb;
        const float* ro = whh + (size_t)(u + 384) * 128 + kb;
#pragma unroll
        for (int q = 0; q < 16; q++) {
            float4 g4 = *(const float4*)&rg[4 * q];
            float4 o4 = *(const float4*)&ro[4 * q];
            ull gp = pku64(bfpk(g4.x, g4.y), bfpk(g4.z, g4.w));
            ull op = pku64(bfpk(o4.x, o4.y), bfpk(o4.z, o4.w));
            wsm[q * 256 + tid] = make_ulonglong2(gp, op);
        }
    }

    // ---- bias + P pointers (half0: gates i,f ; half1: gates g,o) ----
    float bA, bB;
    const float* pA;
    if (half == 0) {
        bA = bias[u];       bB = bias[128 + u];
        pA = g_P + (size_t)b * 1024 + cell * 512 + u;
    } else {
        bA = bias[256 + u]; bB = bias[384 + u];
        pA = g_P + (size_t)b * 1024 + cell * 512 + 256 + u;
    }

    if (tid < 128) hbuf[0][tid] = 0.0f;   // h[-1] = 0
    float c_state = 0.0f;
    int p = 0;
    __syncthreads();

#pragma unroll 1
    for (int t = 0; t < S_LEN; t++) {
        // input projections (independent; LDG hides under matvec)
        float pvA = __ldcg(pA);
        float pvB = __ldcg(pA + 128);
        pA += 65536;                      // next t: +64 rows * 1024

        const float* hb = &hbuf[p][kb];
        ull aI = 0, aF = 0, aG = 0, aO = 0;
#pragma unroll
        for (int q = 0; q < 16; q++) {
            ulonglong2 h2 = *(const ulonglong2*)&hb[4 * q];   // broadcast LDS
            ulonglong2 wp = wsm[q * 256 + tid];               // LDS.128 (bf16 g,o)
            ffma2(aI, h2.x, wi [2 * q]);  ffma2(aI, h2.y, wi [2 * q + 1]);
            ffma2(aF, h2.x, wf_[2 * q]);  ffma2(aF, h2.y, wf_[2 * q + 1]);
            ull g0, g1, o0, o1;
            bf4_unpack(wp.x, g0, g1);
            bf4_unpack(wp.y, o0, o1);
            ffma2(aG, h2.x, g0);  ffma2(aG, h2.y, g1);
            ffma2(aO, h2.x, o0);  ffma2(aO, h2.y, o1);
        }

        float sI = sum2(aI), sF = sum2(aF), sG = sum2(aG), sO = sum2(aO);
        if (half == 0) { sI += pvA + bA; sF += pvB + bB; }
        else           { sG += pvA + bA; sO += pvB + bB; }

        // combine with partner (commutative adds -> bit-identical both sides)
        sI += __shfl_xor_sync(0xffffffffu, sI, 1);
        sF += __shfl_xor_sync(0xffffffffu, sF, 1);
        sG += __shfl_xor_sync(0xffffffffu, sG, 1);
        sO += __shfl_xor_sync(0xffffffffu, sO, 1);

        float si = sigma(sI), sf = sigma(sF);
        float sg = tanha(sG), so = sigma(sO);
        c_state = fmaf(sf, c_state, si * sg);
        float h = so * tanha(c_state);

        if (half == 0) hbuf[p ^ 1][u] = h;
        else           ys[((size_t)t * 64 + b) * 256 + hOff + u] = h;

        __syncthreads();
        p ^= 1;
    }
}

// ---------------------------------------------------------------------------
// out = sigmoid(ys1 @ fc_w^T + fc_b). One warp per row.
// ---------------------------------------------------------------------------
__global__ void __launch_bounds__(256)
k_fc(const float* __restrict__ fc_w, const float* __restrict__ fc_b,
     float* __restrict__ out) {
    int row  = blockIdx.x * 8 + (threadIdx.x >> 5);
    int lane = threadIdx.x & 31;
    const float* y = g_ys1 + (size_t)row * 256;
    float s = 0.0f;
#pragma unroll
    for (int k = lane; k < 256; k += 32) s = fmaf(y[k], fc_w[k], s);
#pragma unroll
    for (int off = 16; off > 0; off >>= 1)
        s += __shfl_xor_sync(0xffffffffu, s, off);
    if (lane == 0) out[row] = sigma(s + fc_b[0]);
}

// ---------------------------------------------------------------------------
// Host entry
// ---------------------------------------------------------------------------
extern "C" void kernel_launch(void* const* d_in, const int* in_sizes, int n_in,
                              void* d_out, int out_size) {
    const float* x     = (const float*)d_in[0];
    const float* wih0f = (const float*)d_in[1];
    const float* whh0f = (const float*)d_in[2];
    const float* b0f   = (const float*)d_in[3];
    const float* wih0b = (const float*)d_in[4];
    const float* whh0b = (const float*)d_in[5];
    const float* b0b   = (const float*)d_in[6];
    const float* wih1f = (const float*)d_in[7];
    const float* whh1f = (const float*)d_in[8];
    const float* b1f   = (const float*)d_in[9];
    const float* wih1b = (const float*)d_in[10];
    const float* whh1b = (const float*)d_in[11];
    const float* b1b   = (const float*)d_in[12];
    const float* fc_w  = (const float*)d_in[13];
    const float* fc_b  = (const float*)d_in[14];
    float* out = (float*)d_out;

    const int smemRec = 65536 + 2 * 128 * 4;   // 66,560 B
    cudaFuncSetAttribute(k_recur5,
                         cudaFuncAttributeMaxDynamicSharedMemorySize, smemRec);

    // layer 0
    k_pack<<<(1024 * 96 + 255) / 256, 256>>>(wih0f, wih0b, 96);
    k_gemm<<<dim3(8, ROWS / 128), 256>>>(x, 0, 96);
    k_recur5<<<128, 256, smemRec>>>(whh0f, whh0b, b0f, b0b, 0);

    // layer 1
    k_pack<<<(1024 * 256 + 255) / 256, 256>>>(wih1f, wih1b, 256);
    k_gemm<<<dim3(8, ROWS / 128), 256>>>(x /*unused*/, 1, 256);
    k_recur5<<<128, 256, smemRec>>>(whh1f, whh1b, b1f, b1b, 1);

    // FC + sigmoid
    k_fc<<<ROWS / 8, 256>>>(fc_w, fc_b, out);
}